// round 12
// baseline (speedup 1.0000x reference)
#include <cuda_runtime.h>

#define NR      96
#define DIM     768
#define TRIU    4560
#define P_CNT   9120
#define Q_CNT   9216
#define THR     0.3f
#define SPLITK  16             // 768/16 = 48 per split
#define KS      48
#define CB      144            // combine blocks (x128 thr)
#define NEG_SL  16
#define NEG_PER 576
#define POS_GR  9
#define HTHR    1024
#define HB      (NEG_SL * POS_GR)   // 144 (proven counter geometry)

// ---------------- device scratch ----------------
__device__ float g_partPos[SPLITK * P_CNT];
__device__ float g_partNeg[SPLITK * Q_CNT];
__device__ float g_partDiag[SPLITK * 2 * NR];
__device__ float g_pos[P_CNT];
__device__ float g_neg[Q_CNT];          // holds (n + THR) * 0.5
__device__ float g_sumP[CB];
__device__ float g_sumN[CB];
__device__ float g_blockSum[HB];
__device__ unsigned g_count = 0;

__device__ __forceinline__ int triu_base(int i) { return i * (191 - i) / 2; }
__device__ __forceinline__ int triu_idx(int i, int j) {
    return triu_base(i) + (j - i - 1);
}

// block reduce; sbuf has 32 slots; works for 128..1024 threads
__device__ __forceinline__ float blockReduce(float v, float* sbuf) {
    __syncthreads();
    int t = threadIdx.x;
    int nw = blockDim.x >> 5;
    #pragma unroll
    for (int o = 16; o; o >>= 1) v += __shfl_down_sync(0xffffffffu, v, o);
    if ((t & 31) == 0) sbuf[t >> 5] = v;
    __syncthreads();
    float r = 0.f;
    if (t < 32) {
        r = (t < nw) ? sbuf[t] : 0.f;
        #pragma unroll
        for (int o = 16; o; o >>= 1) r += __shfl_down_sync(0xffffffffu, r, o);
    }
    return r;   // valid at t == 0
}

// ---------------- K1: RAW grams + diag partials (336 blocks x 256) --------
// K=48 per block; one-shot panel load; 2+ blocks/SM for latency overlap.
__global__ void __launch_bounds__(256) k_gram(const float* __restrict__ S,
                                              const float* __restrict__ A) {
    __shared__ float As[KS][34];
    __shared__ float Bs[KS][34];

    int bx = blockIdx.x;
    int sk = bx / 21;
    int tl = bx % 21;

    int m, tr, tc;
    if (tl < 9) { m = 0; tr = tl / 3; tc = tl % 3; }
    else {
        int q = tl - 9;
        m = 1 + q / 6;
        const int TR6[6] = {0,0,0,1,1,2};
        const int TC6[6] = {0,1,2,1,2,2};
        tr = TR6[q % 6]; tc = TC6[q % 6];
    }
    // m0: neg = A x S^T; m1: S x S^T; m2: A x A^T
    const float* Ap = (m == 1) ? S : A;
    const float* Bp = (m == 2) ? A : S;

    int t  = threadIdx.x;
    int tx = t & 15, ty = t >> 4;
    int kb = sk * KS;

    // ---- prefetch 32x48 panels: 384 float4 per matrix, 256 threads ----
    {
        int row0 = t / 12, f40 = t % 12;          // idx = t (0..255)
        float4 ra0 = *(const float4*)&Ap[(tr * 32 + row0) * DIM + kb + f40 * 4];
        float4 rb0 = *(const float4*)&Bp[(tc * 32 + row0) * DIM + kb + f40 * 4];
        float4 ra1, rb1;
        int row1 = 0, f41 = 0;
        if (t < 128) {                             // idx = 256 + t
            int idx = 256 + t;
            row1 = idx / 12; f41 = idx % 12;
            ra1 = *(const float4*)&Ap[(tr * 32 + row1) * DIM + kb + f41 * 4];
            rb1 = *(const float4*)&Bp[(tc * 32 + row1) * DIM + kb + f41 * 4];
        }
        int k0 = f40 * 4;
        As[k0 + 0][row0] = ra0.x; As[k0 + 1][row0] = ra0.y;
        As[k0 + 2][row0] = ra0.z; As[k0 + 3][row0] = ra0.w;
        Bs[k0 + 0][row0] = rb0.x; Bs[k0 + 1][row0] = rb0.y;
        Bs[k0 + 2][row0] = rb0.z; Bs[k0 + 3][row0] = rb0.w;
        if (t < 128) {
            int k1 = f41 * 4;
            As[k1 + 0][row1] = ra1.x; As[k1 + 1][row1] = ra1.y;
            As[k1 + 2][row1] = ra1.z; As[k1 + 3][row1] = ra1.w;
            Bs[k1 + 0][row1] = rb1.x; Bs[k1 + 1][row1] = rb1.y;
            Bs[k1 + 2][row1] = rb1.z; Bs[k1 + 3][row1] = rb1.w;
        }
    }
    __syncthreads();

    float acc00 = 0.f, acc01 = 0.f, acc10 = 0.f, acc11 = 0.f;
    #pragma unroll 8
    for (int kk = 0; kk < KS; kk++) {
        float2 a = *(const float2*)&As[kk][2 * ty];
        float2 b = *(const float2*)&Bs[kk][2 * tx];
        acc00 += a.x * b.x; acc01 += a.x * b.y;
        acc10 += a.y * b.x; acc11 += a.y * b.y;
    }

    int r0 = tr * 32 + 2 * ty;
    int c0 = tc * 32 + 2 * tx;
    if (m == 0) {
        float* dst = g_partNeg + sk * Q_CNT;
        dst[r0 * 96 + c0]           = acc00;
        dst[r0 * 96 + c0 + 1]       = acc01;
        dst[(r0 + 1) * 96 + c0]     = acc10;
        dst[(r0 + 1) * 96 + c0 + 1] = acc11;
    } else {
        float* dst = g_partPos + sk * P_CNT + ((m == 2) ? TRIU : 0);
        if (r0     < c0    ) dst[triu_idx(r0,     c0    )] = acc00;
        if (r0     < c0 + 1) dst[triu_idx(r0,     c0 + 1)] = acc01;
        if (r0 + 1 < c0    ) dst[triu_idx(r0 + 1, c0    )] = acc10;
        if (r0 + 1 < c0 + 1) dst[triu_idx(r0 + 1, c0 + 1)] = acc11;
        if (r0 == c0) {  // diagonal entries -> squared row norms
            int off = (m == 1) ? 0 : NR;
            g_partDiag[sk * 2 * NR + off + r0]     = acc00;
            g_partDiag[sk * 2 * NR + off + r0 + 1] = acc11;
        }
    }
}

// ---------------- K2: combine + normalize (144 blocks x 128) --------------
__global__ void __launch_bounds__(128) k_combine() {
    __shared__ float s_inv[2 * NR];
    __shared__ float sbuf[32];

    int t   = threadIdx.x;
    int bid = blockIdx.x;

    // inverse norms (128 threads cover 192 entries in 2 steps)
    #pragma unroll
    for (int rr = 0; rr < 2; rr++) {
        int e = t + rr * 128;
        if (e < 2 * NR) {
            float d = 0.f;
            float d0 = 0.f, d1 = 0.f, d2 = 0.f, d3 = 0.f;
            #pragma unroll
            for (int sk = 0; sk < SPLITK; sk += 4) {
                d0 += g_partDiag[(sk + 0) * 192 + e];
                d1 += g_partDiag[(sk + 1) * 192 + e];
                d2 += g_partDiag[(sk + 2) * 192 + e];
                d3 += g_partDiag[(sk + 3) * 192 + e];
            }
            d = (d0 + d1) + (d2 + d3);
            s_inv[e] = 1.0f / fmaxf(sqrtf(d), 1e-8f);
        }
    }
    __syncthreads();

    int e = bid * 128 + t;                        // 0..18431 (< 18336 live)
    float pv = 0.f, nv = 0.f;
    if (e < P_CNT) {
        float r0 = 0.f, r1 = 0.f, r2 = 0.f, r3 = 0.f;
        #pragma unroll
        for (int sk = 0; sk < SPLITK; sk += 4) {
            r0 += g_partPos[(sk + 0) * P_CNT + e];
            r1 += g_partPos[(sk + 1) * P_CNT + e];
            r2 += g_partPos[(sk + 2) * P_CNT + e];
            r3 += g_partPos[(sk + 3) * P_CNT + e];
        }
        float raw = (r0 + r1) + (r2 + r3);
        int invo = (e < TRIU) ? 0 : NR;
        int p    = (e < TRIU) ? e : (e - TRIU);
        // 36481 - 8p exact in fp32 (< 2^24); sqrtf off-by-one fixed below
        int i = (int)((191.0f - sqrtf((float)(36481 - 8 * p))) * 0.5f);
        while (triu_base(i + 1) <= p) ++i;
        while (triu_base(i) > p)      --i;
        int j = p - triu_base(i) + i + 1;
        pv = raw * s_inv[invo + i] * s_inv[invo + j];
        g_pos[e] = pv;
    } else if (e < P_CNT + Q_CNT) {
        int gj = e - P_CNT;
        float r0 = 0.f, r1 = 0.f, r2 = 0.f, r3 = 0.f;
        #pragma unroll
        for (int sk = 0; sk < SPLITK; sk += 4) {
            r0 += g_partNeg[(sk + 0) * Q_CNT + gj];
            r1 += g_partNeg[(sk + 1) * Q_CNT + gj];
            r2 += g_partNeg[(sk + 2) * Q_CNT + gj];
            r3 += g_partNeg[(sk + 3) * Q_CNT + gj];
        }
        float raw = (r0 + r1) + (r2 + r3);
        int r = gj / 96, c = gj % 96;
        nv = raw * s_inv[NR + r] * s_inv[c];
        g_neg[gj] = (nv + THR) * 0.5f;   // halved: hinge uses FFMA x2 (exact)
    }
    float rp = blockReduce(pv, sbuf);
    if (t == 0) g_sumP[bid] = rp;
    float rn = blockReduce(nv, sbuf);
    if (t == 0) g_sumN[bid] = rn;
}

// ---------------- K3: hinge (144 x 1024) + fused final ---------------------
__global__ void __launch_bounds__(HTHR, 1) k_hinge(float* __restrict__ out) {
    __shared__ __align__(16) float s_neg[NEG_PER];
    __shared__ float sbuf[32];
    __shared__ bool s_last;

    int bid = blockIdx.x;
    int ns  = bid / POS_GR;       // 0..15
    int pg  = bid % POS_GR;       // 0..8
    int t   = threadIdx.x;

    // slice of halved negs ((n+THR)/2)
    int j0 = ns * NEG_PER;
    if (t < NEG_PER) s_neg[t] = g_neg[j0 + t];

    int pid = pg * HTHR + t;      // max 9215
    bool act = (pid < P_CNT);
    float c = act ? -g_pos[pid] : 0.f;
    __syncthreads();

    // main hinge: x = FFMA(v, 2.0, c) [imm mult, rt=1]; acc += |x| [FADD rt=2]
    float s0 = 0.f, s1 = 0.f, s2 = 0.f, s3 = 0.f;
    const float4* sn4 = reinterpret_cast<const float4*>(s_neg);  // 144 vecs
    #pragma unroll 6
    for (int i = 0; i < NEG_PER / 4; i++) {
        float4 v = sn4[i];
        s0 += fabsf(__fmaf_rn(v.x, 2.0f, c));
        s1 += fabsf(__fmaf_rn(v.y, 2.0f, c));
        s2 += fabsf(__fmaf_rn(v.z, 2.0f, c));
        s3 += fabsf(__fmaf_rn(v.w, 2.0f, c));
    }
    float accf = act ? ((s0 + s1) + (s2 + s3)) : 0.f;

    float bsum = blockReduce(accf, sbuf);
    if (t == 0) g_blockSum[bid] = bsum;

    // last-block-done deterministic final combine (proven HB=144 pattern)
    if (t == 0) {
        __threadfence();
        unsigned old = atomicInc(&g_count, HB - 1);
        s_last = (old == HB - 1);
    }
    __syncthreads();
    if (!s_last) return;
    __threadfence();

    float vA = (t < HB) ? g_blockSum[t] : 0.f;
    float S_abs = blockReduce(vA, sbuf);
    float vP = (t < CB) ? g_sumP[t] : 0.f;
    float S_pos = blockReduce(vP, sbuf);
    float vN = (t < CB) ? g_sumN[t] : 0.f;
    float S_neg = blockReduce(vN, sbuf);

    if (t == 0) {
        const double P = (double)P_CNT, Q = (double)Q_CNT, thr = (double)THR;
        double Sx = P * (double)S_neg - Q * (double)S_pos + P * Q * thr;
        out[0] = (float)(0.5 * (Sx + (double)S_abs) / (P * Q));
    }
}

// ---------------- launch ----------------
extern "C" void kernel_launch(void* const* d_in, const int* in_sizes, int n_in,
                              void* d_out, int out_size) {
    const float* stereos  = (const float*)d_in[0];
    const float* astereos = (const float*)d_in[1];
    k_gram<<<21 * SPLITK, 256>>>(stereos, astereos);
    k_combine<<<CB, 128>>>();
    k_hinge<<<HB, HTHR>>>((float*)d_out);
}